// round 9
// baseline (speedup 1.0000x reference)
#include <cuda_runtime.h>

#define BB 128
#define TT 256
#define DD 256
#define UU 256
#define ZZ 1024   // 4*U
#define CLUSTER 8

// ---------------- scratch (device globals; no allocation allowed) ----------------
__device__ float g_xz[2][TT * BB * ZZ];       // [dir][t][b][u*4+g]
__device__ float g_h0[2][TT * BB * UU];       // layer-0 outputs [dir][t][b][u]
__device__ float g_h1[2][TT * BB * UU];       // layer-1 raw lstm outputs
__device__ float g_Wp[2][2][DD * ZZ];         // [layer][dir][k][u*4+g]
__device__ float g_Rp[2][2][UU * ZZ];         // [layer][dir][k][u*4+g]
__device__ float g_bp[2][2][ZZ];

// ---------------- packed f32x2 (FFMA2) helpers ------------------------------------
__device__ __forceinline__ void fma2(unsigned long long& d, unsigned long long a,
                                     unsigned long long b) {
    asm("fma.rn.f32x2 %0, %1, %2, %0;" : "+l"(d) : "l"(a), "l"(b));
}
__device__ __forceinline__ void add2(unsigned long long& d, unsigned long long a) {
    asm("add.rn.f32x2 %0, %0, %1;" : "+l"(d) : "l"(a));
}
__device__ __forceinline__ unsigned long long pack2(float x) {
    unsigned long long d; unsigned int u = __float_as_uint(x);
    asm("mov.b64 %0, {%1, %1};" : "=l"(d) : "r"(u));
    return d;
}
__device__ __forceinline__ void unpack2(unsigned long long v, float& lo, float& hi) {
    unsigned int a, b;
    asm("mov.b64 {%0, %1}, %2;" : "=r"(a), "=r"(b) : "l"(v));
    lo = __uint_as_float(a); hi = __uint_as_float(b);
}

// ---------------- cluster / DSMEM helpers ------------------------------------------
__device__ __forceinline__ unsigned mapa32(unsigned saddr, unsigned rank) {
    unsigned r;
    asm("mapa.shared::cluster.u32 %0, %1, %2;" : "=r"(r) : "r"(saddr), "r"(rank));
    return r;
}
__device__ __forceinline__ void st_cluster4(unsigned addr, float4 v) {
    asm volatile("st.shared::cluster.v4.f32 [%0], {%1, %2, %3, %4};"
                 :: "r"(addr), "f"(v.x), "f"(v.y), "f"(v.z), "f"(v.w) : "memory");
}
__device__ __forceinline__ void cluster_sync() {
    asm volatile("barrier.cluster.arrive.aligned;" ::: "memory");
    asm volatile("barrier.cluster.wait.aligned;" ::: "memory");
}

// ---------------- cp.async helpers -------------------------------------------------
__device__ __forceinline__ void cpa16(void* smem, const void* g) {
    unsigned s = (unsigned)__cvta_generic_to_shared(smem);
    asm volatile("cp.async.cg.shared.global [%0], [%1], 16;" :: "r"(s), "l"(g));
}
__device__ __forceinline__ void cpa_commit() { asm volatile("cp.async.commit_group;"); }
__device__ __forceinline__ void cpa_wait0()  { asm volatile("cp.async.wait_group 0;"); }

// ---------------- MUFU-free fast math ---------------------------------------------
__device__ __forceinline__ float fast_exp(float x) {
    x = fminf(fmaxf(x, -80.0f), 80.0f);
    float y = x * 1.442695041f;
    float t = y + 12582912.0f;
    float n = t - 12582912.0f;
    float f = y - n;
    int   ni = __float_as_int(t) - 0x4B400000;
    float p = 1.54035304e-4f;
    p = fmaf(p, f, 1.33335581e-3f);
    p = fmaf(p, f, 9.61812910e-3f);
    p = fmaf(p, f, 5.55041087e-2f);
    p = fmaf(p, f, 2.40226507e-1f);
    p = fmaf(p, f, 6.93147182e-1f);
    p = fmaf(p, f, 1.0f);
    return p * __int_as_float((ni + 127) << 23);
}
__device__ __forceinline__ float fast_rcp(float a) {
    float r = __int_as_float(0x7EF311C3 - __float_as_int(a));
    r = r * fmaf(-a, r, 2.0f);
    r = r * fmaf(-a, r, 2.0f);
    r = r * fmaf(-a, r, 2.0f);
    return r;
}
__device__ __forceinline__ float sigm_(float x) { return fast_rcp(1.0f + fast_exp(-x)); }
__device__ __forceinline__ float tanh_(float x) { return fmaf(-2.0f, fast_rcp(1.0f + fast_exp(2.0f * x)), 1.0f); }

// ---------------- weight permutation: col (g*256+u) -> (u*4+g) --------------------
__global__ void prep_kernel(const float* __restrict__ kfw, const float* __restrict__ rfw,
                            const float* __restrict__ bfw, const float* __restrict__ kbw,
                            const float* __restrict__ rbw, const float* __restrict__ bbw) {
    int idx = blockIdx.x * blockDim.x + threadIdx.x;
    if (idx >= 2 * 2 * DD * ZZ) return;
    int e  = idx & (DD * ZZ - 1);
    int ld = idx >> 18;
    int l = ld >> 1, d = ld & 1;
    int k  = e >> 10;
    int uu = e & 1023;
    int u = uu >> 2, g = uu & 3;
    int src_col = g * UU + u;
    const float* Ksrc = d ? kbw : kfw;
    const float* Rsrc = d ? rbw : rfw;
    g_Wp[l][d][e] = Ksrc[l * DD * ZZ + k * ZZ + src_col];
    g_Rp[l][d][e] = Rsrc[l * UU * ZZ + k * ZZ + src_col];
    if (k == 0) {
        const float* bsrc = d ? bbw : bfw;
        g_bp[l][d][uu] = bsrc[l * ZZ + src_col];
    }
}

// ---------------- input projection (FFMA2 + cp.async double buffer) ----------------
__global__ __launch_bounds__(256, 2) void proj_kernel(const float* __restrict__ x, int layer) {
    int dir = blockIdx.z;
    const float* A  = (layer == 0) ? x : g_h0[dir];
    const float* Wp = g_Wp[layer][dir];
    const float* bp = g_bp[layer][dir];
    float* C = g_xz[dir];
    const int m0 = blockIdx.y * 128;
    const int n0 = blockIdx.x * 128;
    __shared__ float As[2][8][128];
    __shared__ float Bs[2][8][128];
    int tid = threadIdx.x;
    int tm = (tid >> 4) << 3;
    int tn = (tid & 15) << 3;
    unsigned long long acc2[8][4];
#pragma unroll
    for (int i = 0; i < 8; i++)
#pragma unroll
        for (int j = 0; j < 4; j++) acc2[i][j] = 0ULL;

    int arow = tid >> 1, akq = (tid & 1) << 2;
    int brow = tid >> 5, bc = (tid & 31) << 2;
    const float* Ap = A + (size_t)(m0 + arow) * DD + akq;
    const float* Bp = Wp + (size_t)brow * ZZ + n0 + bc;

    {
        float4 av0 = *(const float4*)Ap;
        As[0][akq + 0][arow] = av0.x;
        As[0][akq + 1][arow] = av0.y;
        As[0][akq + 2][arow] = av0.z;
        As[0][akq + 3][arow] = av0.w;
    }
    cpa16(&Bs[0][brow][bc], Bp);
    cpa_commit();
    float4 avn = *(const float4*)(Ap + 8);

    for (int it = 0; it < 32; it++) {
        int cur = it & 1, nxt = cur ^ 1;
        cpa_wait0();
        __syncthreads();
        if (it < 31) {
            As[nxt][akq + 0][arow] = avn.x;
            As[nxt][akq + 1][arow] = avn.y;
            As[nxt][akq + 2][arow] = avn.z;
            As[nxt][akq + 3][arow] = avn.w;
            cpa16(&Bs[nxt][brow][bc], Bp + (size_t)(it + 1) * 8 * ZZ);
            cpa_commit();
            if (it < 30) avn = *(const float4*)(Ap + (it + 2) * 8);
        }
#pragma unroll
        for (int kk = 0; kk < 8; kk++) {
            float a[8];
            *(float4*)&a[0] = *(float4*)&As[cur][kk][tm];
            *(float4*)&a[4] = *(float4*)&As[cur][kk][tm + 4];
            ulonglong2 b01 = *(const ulonglong2*)&Bs[cur][kk][tn];
            ulonglong2 b23 = *(const ulonglong2*)&Bs[cur][kk][tn + 4];
#pragma unroll
            for (int i = 0; i < 8; i++) {
                unsigned long long ai = pack2(a[i]);
                fma2(acc2[i][0], ai, b01.x);
                fma2(acc2[i][1], ai, b01.y);
                fma2(acc2[i][2], ai, b23.x);
                fma2(acc2[i][3], ai, b23.y);
            }
        }
    }
    float bv[8];
#pragma unroll
    for (int j = 0; j < 8; j++) bv[j] = bp[n0 + tn + j];
#pragma unroll
    for (int i = 0; i < 8; i++) {
        int m = m0 + tm + i;
        int crow = (layer == 0) ? ((m & 255) * BB + (m >> 8)) : m;
        float* cp = C + (size_t)crow * ZZ + n0 + tn;
        float c0, c1, c2, c3, c4, c5, c6, c7;
        unpack2(acc2[i][0], c0, c1);
        unpack2(acc2[i][1], c2, c3);
        unpack2(acc2[i][2], c4, c5);
        unpack2(acc2[i][3], c6, c7);
        float4 v0, v1;
        v0.x = c0 + bv[0]; v0.y = c1 + bv[1]; v0.z = c2 + bv[2]; v0.w = c3 + bv[3];
        v1.x = c4 + bv[4]; v1.y = c5 + bv[5]; v1.z = c6 + bv[6]; v1.w = c7 + bv[7];
        *(float4*)cp = v0;
        *(float4*)(cp + 4) = v1;
    }
}

// ---------------- persistent cluster scan (one launch per layer) -------------------
// grid 128 CTAs x 512 threads, clusters of 8. CTA = (dir, batch-16th b0g..+15,
// z-slice zi of 128 z-cols = 32 units). Cluster = the 8 z-slices sharing (dir,bq):
// together they produce the full 256-unit h for their 16 batches each step and
// exchange it via DSMEM. One barrier.cluster per step; h tile double-buffered.
// R slice (128KB) resident in smem; c in registers. Clusters are independent.
__global__ void __cluster_dims__(CLUSTER, 1, 1) __launch_bounds__(512, 1)
scan_kernel(int layer) {
    extern __shared__ float sm[];
    float* Rs  = sm;                        // [256 k][128 zc]  = 128 KB
    float* hb0 = sm + 256 * 128;            // [256 k][16 b]    = 16 KB
    float* hb1 = hb0 + 256 * 16;            // 16 KB
    unsigned long long* red = (unsigned long long*)(hb1 + 256 * 16); // 3*128*8 = 24 KB
    float* stg_h = (float*)(red + 384 * 8); // [32 u][16 b] 2 KB
    float* stg_o = stg_h + 512;             // [16 b][32 u] 2 KB

    int bid = blockIdx.x;
    int dir = bid >> 6;
    int bqg = (bid >> 3) & 7;     // batch group of 16
    int zi  = bid & 7;            // cluster rank == z-slice
    int b0g = bqg * 16;
    int tid = threadIdx.x;
    int kq  = tid >> 7;           // k quarter 0..3
    int wtid = tid & 127;
    int bp  = wtid & 7;           // batch pair (2 b)
    int zs  = wtid >> 3;          // 0..15: 8 z-cols = 2 units

    // load R slice [256 k][128 zc] once (resident all 256 steps)
    {
        const float* Rp = g_Rp[layer][dir] + zi * 128;
        for (int i = tid; i < 8192; i += 512) {
            int k = i >> 5, c = (i & 31) << 2;
            *(float4*)&Rs[k * 128 + c] = *(const float4*)(Rp + (size_t)k * ZZ + c);
        }
    }
    // zero h buffer 0 (step-0 state)
    for (int i = tid; i < 1024; i += 512)
        ((float4*)hb0)[i] = make_float4(0.f, 0.f, 0.f, 0.f);

    unsigned hb0a = (unsigned)__cvta_generic_to_shared(hb0);
    unsigned hb1a = (unsigned)__cvta_generic_to_shared(hb1);

    const float* xzb  = g_xz[dir];
    float*       outb = (layer == 0) ? g_h0[dir] : g_h1[dir];
    float cc[2][2] = {{0.f, 0.f}, {0.f, 0.f}};

    cluster_sync();   // all tiles initialized before any DSMEM traffic

    for (int s = 0; s < TT; s++) {
        int t = dir ? (TT - 1 - s) : s;
        const float* hs = (s & 1) ? hb1 : hb0;
        unsigned wrbase = ((s & 1) ? hb0a : hb1a) + (unsigned)(zi * 512 * 4); // my 32-unit rows

        // xz prefetch for gate phase (kq==0 only) — hidden under GEMM
        float4 xv[2][2];
        if (kq == 0) {
            const float* xp = xzb + (size_t)(t * BB + b0g + 2 * bp) * ZZ + zi * 128 + zs * 8;
            xv[0][0] = *(const float4*)(xp);
            xv[0][1] = *(const float4*)(xp + 4);
            xv[1][0] = *(const float4*)(xp + ZZ);
            xv[1][1] = *(const float4*)(xp + ZZ + 4);
        }

        // GEMM quarter: acc (2 b x 8 zc) over 64 k
        unsigned long long acc[8];
#pragma unroll
        for (int j = 0; j < 8; j++) acc[j] = 0ULL;
        {
            const float* hrow = hs + kq * 64 * 16 + bp * 2;
            const float* rrow = Rs + kq * 64 * 128 + zs * 8;
#pragma unroll 4
            for (int k = 0; k < 64; k++) {
                float2 hp = *(const float2*)(hrow + k * 16);
                ulonglong2 r01 = *(const ulonglong2*)(rrow + k * 128);
                ulonglong2 r23 = *(const ulonglong2*)(rrow + k * 128 + 4);
                unsigned long long h0 = pack2(hp.x), h1 = pack2(hp.y);
                fma2(acc[0], h0, r01.x); fma2(acc[1], h0, r01.y);
                fma2(acc[2], h0, r23.x); fma2(acc[3], h0, r23.y);
                fma2(acc[4], h1, r01.x); fma2(acc[5], h1, r01.y);
                fma2(acc[6], h1, r23.x); fma2(acc[7], h1, r23.y);
            }
        }
        if (kq) {
#pragma unroll
            for (int j = 0; j < 8; j++) red[((kq - 1) * 128 + wtid) * 8 + j] = acc[j];
        }
        __syncthreads();
        if (kq == 0) {
#pragma unroll
            for (int q = 0; q < 3; q++)
#pragma unroll
                for (int j = 0; j < 8; j++) add2(acc[j], red[(q * 128 + wtid) * 8 + j]);
            // gates for 4 cells: (2 b) x (2 units)
#pragma unroll
            for (int bi = 0; bi < 2; bi++) {
#pragma unroll
                for (int ui = 0; ui < 2; ui++) {
                    float z0, z1, z2, z3;
                    unpack2(acc[bi * 4 + ui * 2 + 0], z0, z1);
                    unpack2(acc[bi * 4 + ui * 2 + 1], z2, z3);
                    float4 xq = xv[bi][ui];
                    z0 += xq.x; z1 += xq.y; z2 += xq.z; z3 += xq.w;
                    float ig = sigm_(z0);
                    float fg = sigm_(z1);
                    float gg = tanh_(z2);
                    float og = sigm_(z3);
                    float cn = fmaf(fg, cc[bi][ui], ig * gg);
                    cc[bi][ui] = cn;
                    float hn = og * tanh_(cn);
                    int ul = 2 * zs + ui, b = 2 * bp + bi;
                    stg_h[ul * 16 + b] = hn;
                    stg_o[b * 32 + ul] = hn;
                }
            }
        }
        __syncthreads();

        // DSMEM broadcast: my 32-unit h slice -> all 8 cluster CTAs' write buffer
        {
            int rank = tid >> 6;          // 0..7
            int j    = tid & 63;          // 2 float4 each (128 float4 total)
            unsigned dst = mapa32(wrbase, (unsigned)rank) + (unsigned)(j * 32);
            float4 v0 = ((const float4*)stg_h)[j * 2];
            float4 v1 = ((const float4*)stg_h)[j * 2 + 1];
            st_cluster4(dst, v0);
            st_cluster4(dst + 16, v1);
        }
        // sequence output [t][b][u] (coalesced)
        if (tid < 128) {
            int b = tid >> 3, q = tid & 7;
            *(float4*)(outb + (size_t)(t * BB + b0g + b) * UU + zi * 32 + q * 4) =
                *(const float4*)&stg_o[b * 32 + q * 4];
        }
        cluster_sync();   // release my stores, acquire everyone's h for next step
    }
}

// ---------------- merge: out[b][t][u] = 0.5*(h1f + h0f + h1b + h0b) ---------------
__global__ void merge_kernel(float* __restrict__ out) {
    int i = blockIdx.x * blockDim.x + threadIdx.x;
    if (i >= TT * BB * UU / 4) return;
    int u4 = i & 63;
    int b  = (i >> 6) & 127;
    int t  = i >> 13;
    const float4 a = ((const float4*)g_h1[0])[i];
    const float4 c = ((const float4*)g_h0[0])[i];
    const float4 d = ((const float4*)g_h1[1])[i];
    const float4 e = ((const float4*)g_h0[1])[i];
    float4 r;
    r.x = 0.5f * (a.x + c.x + d.x + e.x);
    r.y = 0.5f * (a.y + c.y + d.y + e.y);
    r.z = 0.5f * (a.z + c.z + d.z + e.z);
    r.w = 0.5f * (a.w + c.w + d.w + e.w);
    ((float4*)out)[((b * TT + t) << 6) + u4] = r;
}

// ---------------- launch ----------------------------------------------------------
extern "C" void kernel_launch(void* const* d_in, const int* in_sizes, int n_in,
                              void* d_out, int out_size) {
    const float* x   = (const float*)d_in[0];
    const float* kfw = (const float*)d_in[1];
    const float* rfw = (const float*)d_in[2];
    const float* bfw = (const float*)d_in[3];
    const float* kbw = (const float*)d_in[4];
    const float* rbw = (const float*)d_in[5];
    const float* bbw = (const float*)d_in[6];
    float* out = (float*)d_out;

    // Rs 128K + h 2x16K + red 24K + stages 4K = 192512 bytes
    const int scan_smem = (256 * 128 + 2 * 256 * 16 + 384 * 8 * 2 + 1024) * (int)sizeof(float);
    cudaFuncSetAttribute(scan_kernel, cudaFuncAttributeMaxDynamicSharedMemorySize, scan_smem);

    prep_kernel<<<4096, 256>>>(kfw, rfw, bfw, kbw, rbw, bbw);
    for (int layer = 0; layer < 2; layer++) {
        proj_kernel<<<dim3(8, 256, 2), 256>>>(x, layer);
        scan_kernel<<<128, 512, scan_smem>>>(layer);
    }
    merge_kernel<<<8192, 256>>>(out);
}

// round 10
// speedup vs baseline: 1.5704x; 1.5704x over previous
#include <cuda_runtime.h>

#define BB 128
#define TT 256
#define DD 256
#define UU 256
#define ZZ 1024   // 4*U
#define NCTA 128

// ---------------- scratch (device globals; no allocation allowed) ----------------
__device__ float g_xz[2][TT * BB * ZZ];       // [dir][t][b][u*4+g]
__device__ float g_h0[2][TT * BB * UU];       // layer-0 outputs [dir][t][b][u]
__device__ float g_h1[2][TT * BB * UU];       // layer-1 raw lstm outputs
__device__ float g_hT[2][2][UU * BB];         // [buf][dir][u][b] double-buffered h^T
__device__ float g_Wp[2][2][DD * ZZ];         // [layer][dir][k][u*4+g]
__device__ float g_Rp[2][2][UU * ZZ];         // [layer][dir][k][u*4+g]
__device__ float g_bp[2][2][ZZ];
__device__ int g_count[8];                    // per-group barrier (dir x batch-quarter)
__device__ int g_gen[8];

// ---------------- packed f32x2 (FFMA2) helpers ------------------------------------
__device__ __forceinline__ void fma2(unsigned long long& d, unsigned long long a,
                                     unsigned long long b) {
    asm("fma.rn.f32x2 %0, %1, %2, %0;" : "+l"(d) : "l"(a), "l"(b));
}
__device__ __forceinline__ void add2(unsigned long long& d, unsigned long long a) {
    asm("add.rn.f32x2 %0, %0, %1;" : "+l"(d) : "l"(a));
}
__device__ __forceinline__ unsigned long long pack2(float x) {
    unsigned long long d; unsigned int u = __float_as_uint(x);
    asm("mov.b64 %0, {%1, %1};" : "=l"(d) : "r"(u));
    return d;
}
__device__ __forceinline__ void unpack2(unsigned long long v, float& lo, float& hi) {
    unsigned int a, b;
    asm("mov.b64 {%0, %1}, %2;" : "=r"(a), "=r"(b) : "l"(v));
    lo = __uint_as_float(a); hi = __uint_as_float(b);
}

// ---------------- acquire/release barrier primitives (CG grid.sync pattern) --------
__device__ __forceinline__ int atom_add_acqrel(int* p) {
    int old;
    asm volatile("atom.acq_rel.gpu.global.add.s32 %0, [%1], 1;"
                 : "=r"(old) : "l"(p) : "memory");
    return old;
}
__device__ __forceinline__ void st_release(int* p, int v) {
    asm volatile("st.release.gpu.global.s32 [%0], %1;" :: "l"(p), "r"(v) : "memory");
}
__device__ __forceinline__ int ld_acquire(int* p) {
    int v;
    asm volatile("ld.acquire.gpu.global.s32 %0, [%1];" : "=r"(v) : "l"(p) : "memory");
    return v;
}

// ---------------- cp.async helpers -------------------------------------------------
__device__ __forceinline__ void cpa16(void* smem, const void* g) {
    unsigned s = (unsigned)__cvta_generic_to_shared(smem);
    asm volatile("cp.async.cg.shared.global [%0], [%1], 16;" :: "r"(s), "l"(g));
}
__device__ __forceinline__ void cpa_commit() { asm volatile("cp.async.commit_group;"); }
__device__ __forceinline__ void cpa_wait0()  { asm volatile("cp.async.wait_group 0;"); }

// ---------------- MUFU-free fast math ---------------------------------------------
__device__ __forceinline__ float fast_exp(float x) {
    x = fminf(fmaxf(x, -80.0f), 80.0f);
    float y = x * 1.442695041f;
    float t = y + 12582912.0f;
    float n = t - 12582912.0f;
    float f = y - n;
    int   ni = __float_as_int(t) - 0x4B400000;
    float p = 1.54035304e-4f;
    p = fmaf(p, f, 1.33335581e-3f);
    p = fmaf(p, f, 9.61812910e-3f);
    p = fmaf(p, f, 5.55041087e-2f);
    p = fmaf(p, f, 2.40226507e-1f);
    p = fmaf(p, f, 6.93147182e-1f);
    p = fmaf(p, f, 1.0f);
    return p * __int_as_float((ni + 127) << 23);
}
__device__ __forceinline__ float fast_rcp(float a) {
    float r = __int_as_float(0x7EF311C3 - __float_as_int(a));
    r = r * fmaf(-a, r, 2.0f);
    r = r * fmaf(-a, r, 2.0f);
    r = r * fmaf(-a, r, 2.0f);
    return r;
}
__device__ __forceinline__ float sigm_(float x) { return fast_rcp(1.0f + fast_exp(-x)); }
__device__ __forceinline__ float tanh_(float x) { return fmaf(-2.0f, fast_rcp(1.0f + fast_exp(2.0f * x)), 1.0f); }

// ---------------- weight permutation: col (g*256+u) -> (u*4+g) --------------------
__global__ void prep_kernel(const float* __restrict__ kfw, const float* __restrict__ rfw,
                            const float* __restrict__ bfw, const float* __restrict__ kbw,
                            const float* __restrict__ rbw, const float* __restrict__ bbw) {
    int idx = blockIdx.x * blockDim.x + threadIdx.x;
    if (idx >= 2 * 2 * DD * ZZ) return;
    int e  = idx & (DD * ZZ - 1);
    int ld = idx >> 18;
    int l = ld >> 1, d = ld & 1;
    int k  = e >> 10;
    int uu = e & 1023;
    int u = uu >> 2, g = uu & 3;
    int src_col = g * UU + u;
    const float* Ksrc = d ? kbw : kfw;
    const float* Rsrc = d ? rbw : rfw;
    g_Wp[l][d][e] = Ksrc[l * DD * ZZ + k * ZZ + src_col];
    g_Rp[l][d][e] = Rsrc[l * UU * ZZ + k * ZZ + src_col];
    if (k == 0) {
        const float* bsrc = d ? bbw : bfw;
        g_bp[l][d][uu] = bsrc[l * ZZ + src_col];
    }
}

__global__ void zero_bar_kernel() {
    if (threadIdx.x < 8) { g_count[threadIdx.x] = 0; g_gen[threadIdx.x] = 0; }
}

// ---------------- input projection (FFMA2, cp.async double buffer, KTILE=16) -------
__global__ __launch_bounds__(256, 2) void proj_kernel(const float* __restrict__ x, int layer) {
    int dir = blockIdx.z;
    const float* A  = (layer == 0) ? x : g_h0[dir];
    const float* Wp = g_Wp[layer][dir];
    const float* bp = g_bp[layer][dir];
    float* C = g_xz[dir];
    const int m0 = blockIdx.y * 128;
    const int n0 = blockIdx.x * 128;
    __shared__ float As[2][16][128];
    __shared__ float Bs[2][16][128];
    int tid = threadIdx.x;
    int tm = (tid >> 4) << 3;
    int tn = (tid & 15) << 3;
    unsigned long long acc2[8][4];
#pragma unroll
    for (int i = 0; i < 8; i++)
#pragma unroll
        for (int j = 0; j < 4; j++) acc2[i][j] = 0ULL;

    int arow = tid >> 1, akq = (tid & 1) << 3;   // 0 or 8
    int brow = tid >> 4, bc = (tid & 15) << 3;   // 16 rows x (8 floats per thread)
    const float* Ap = A + (size_t)(m0 + arow) * DD + akq;
    const float* Bp = Wp + (size_t)brow * ZZ + n0 + bc;

    // prologue: tile 0 staged, tile 1 A prefetched
    {
        float4 a0 = *(const float4*)Ap;
        float4 a1 = *(const float4*)(Ap + 4);
        As[0][akq + 0][arow] = a0.x; As[0][akq + 1][arow] = a0.y;
        As[0][akq + 2][arow] = a0.z; As[0][akq + 3][arow] = a0.w;
        As[0][akq + 4][arow] = a1.x; As[0][akq + 5][arow] = a1.y;
        As[0][akq + 6][arow] = a1.z; As[0][akq + 7][arow] = a1.w;
    }
    cpa16(&Bs[0][brow][bc], Bp);
    cpa16(&Bs[0][brow][bc + 4], Bp + 4);
    cpa_commit();
    float4 av0 = *(const float4*)(Ap + 16);
    float4 av1 = *(const float4*)(Ap + 20);

    for (int it = 0; it < 16; it++) {
        int cur = it & 1, nxt = cur ^ 1;
        cpa_wait0();
        __syncthreads();
        if (it < 15) {
            As[nxt][akq + 0][arow] = av0.x; As[nxt][akq + 1][arow] = av0.y;
            As[nxt][akq + 2][arow] = av0.z; As[nxt][akq + 3][arow] = av0.w;
            As[nxt][akq + 4][arow] = av1.x; As[nxt][akq + 5][arow] = av1.y;
            As[nxt][akq + 6][arow] = av1.z; As[nxt][akq + 7][arow] = av1.w;
            cpa16(&Bs[nxt][brow][bc], Bp + (size_t)(it + 1) * 16 * ZZ);
            cpa16(&Bs[nxt][brow][bc + 4], Bp + (size_t)(it + 1) * 16 * ZZ + 4);
            cpa_commit();
            if (it < 14) {
                av0 = *(const float4*)(Ap + (it + 2) * 16);
                av1 = *(const float4*)(Ap + (it + 2) * 16 + 4);
            }
        }
#pragma unroll
        for (int kk = 0; kk < 16; kk++) {
            float a[8];
            *(float4*)&a[0] = *(float4*)&As[cur][kk][tm];
            *(float4*)&a[4] = *(float4*)&As[cur][kk][tm + 4];
            ulonglong2 b01 = *(const ulonglong2*)&Bs[cur][kk][tn];
            ulonglong2 b23 = *(const ulonglong2*)&Bs[cur][kk][tn + 4];
#pragma unroll
            for (int i = 0; i < 8; i++) {
                unsigned long long ai = pack2(a[i]);
                fma2(acc2[i][0], ai, b01.x);
                fma2(acc2[i][1], ai, b01.y);
                fma2(acc2[i][2], ai, b23.x);
                fma2(acc2[i][3], ai, b23.y);
            }
        }
    }
    float bv[8];
#pragma unroll
    for (int j = 0; j < 8; j++) bv[j] = bp[n0 + tn + j];
#pragma unroll
    for (int i = 0; i < 8; i++) {
        int m = m0 + tm + i;
        int crow = (layer == 0) ? ((m & 255) * BB + (m >> 8)) : m;
        float* cp = C + (size_t)crow * ZZ + n0 + tn;
        float c0, c1, c2, c3, c4, c5, c6, c7;
        unpack2(acc2[i][0], c0, c1);
        unpack2(acc2[i][1], c2, c3);
        unpack2(acc2[i][2], c4, c5);
        unpack2(acc2[i][3], c6, c7);
        float4 v0, v1;
        v0.x = c0 + bv[0]; v0.y = c1 + bv[1]; v0.z = c2 + bv[2]; v0.w = c3 + bv[3];
        v1.x = c4 + bv[4]; v1.y = c5 + bv[5]; v1.z = c6 + bv[6]; v1.w = c7 + bv[7];
        *(float4*)cp = v0;
        *(float4*)(cp + 4) = v1;
    }
}

// ---------------- persistent recurrence scan (one launch per layer) ----------------
// grid 128 CTAs x 256 threads. CTA = (dir, batch-quarter 32b, z-slice 64zc = 16 units).
// Barrier groups of 16 CTAs sharing (dir,bq). R resident in smem; c in registers.
// Epilogue (reduction + gates) split across ALL 256 threads (2 cells each).
__global__ __launch_bounds__(256, 1) void scan_kernel(int layer) {
    extern __shared__ float sm[];
    float* Rs = sm;                                   // 256*64 = 64 KB
    float* hs = sm + UU * 64;                         // 256*32 = 32 KB
    unsigned long long* red = (unsigned long long*)(hs + UU * 32);  // 256*8 u64 = 16 KB
    float* stage = (float*)(red + 256 * 8);           // 2 KB

    int bid = blockIdx.x;
    int dir  = bid >> 6;
    int rest = bid & 63;
    int b0  = (rest >> 4) * 32;      // batch quarter
    int zi  = rest & 15;             // z slice
    int zc0 = zi * 64;
    int u0  = zi * 16;
    int grp = bid >> 4;              // dir*4 + batch-quarter
    int tid = threadIdx.x;
    int kh   = tid >> 7;             // k half
    int wtid = tid & 127;
    int zg  = wtid & 15;             // unit within slice
    int bgr = wtid >> 4;             // batch group of 4
    int bb  = b0 + bgr * 4 + kh * 2; // this thread's 2 batch rows (epilogue)

    // load R slice once (resident for all 256 steps)
    {
        const float* Rp = g_Rp[layer][dir];
        float4* Rs4 = (float4*)Rs;
        for (int idx = tid; idx < 4096; idx += 256) {
            int k = idx >> 4, c = idx & 15;
            Rs4[idx] = *(const float4*)(Rp + k * ZZ + zc0 + c * 4);
        }
    }
    float cc[2] = {0.0f, 0.0f};
    const float* xzb  = g_xz[dir];
    float*       outb = (layer == 0) ? g_h0[dir] : g_h1[dir];

    // prefetch xz for step 0 (this thread's 2 cells)
    float4 xv[2];
    {
        int t0 = dir ? (TT - 1) : 0;
        const float* xp = xzb + (size_t)(t0 * BB + bb) * ZZ + zc0 + zg * 4;
        xv[0] = *(const float4*)(xp);
        xv[1] = *(const float4*)(xp + ZZ);
    }
    __syncthreads();

    for (int s = 0; s < TT; s++) {
        int t  = dir ? (TT - 1 - s) : s;
        int rd = s & 1, wr = rd ^ 1;

        // fill h tile [256 k][32 b] from g_hT[rd] via cp.async.cg (L2 path)
        float4* hs4 = (float4*)hs;
        if (s == 0) {
            for (int idx = tid; idx < 2048; idx += 256)
                hs4[idx] = make_float4(0.f, 0.f, 0.f, 0.f);
        } else {
            const float4* src = (const float4*)(g_hT[rd][dir]);
            for (int idx = tid; idx < 2048; idx += 256) {
                int k = idx >> 3, q = idx & 7;
                cpa16(&hs4[idx], src + k * 32 + (b0 >> 2) + q);
            }
            cpa_commit();
            cpa_wait0();
        }
        __syncthreads();

        // GEMM half: acc(4b x 4zc) over 128 k
        unsigned long long acc[8];
#pragma unroll
        for (int j = 0; j < 8; j++) acc[j] = 0ULL;
        {
            const float* hrow = hs + kh * 128 * 32 + bgr * 4;
            const float* rrow = Rs + kh * 128 * 64 + zg * 4;
#pragma unroll 4
            for (int k = 0; k < 128; k++) {
                float4 hv = *(const float4*)(hrow + k * 32);
                ulonglong2 rv = *(const ulonglong2*)(rrow + k * 64);
                unsigned long long h0 = pack2(hv.x), h1 = pack2(hv.y);
                unsigned long long h2 = pack2(hv.z), h3 = pack2(hv.w);
                fma2(acc[0], h0, rv.x); fma2(acc[1], h0, rv.y);
                fma2(acc[2], h1, rv.x); fma2(acc[3], h1, rv.y);
                fma2(acc[4], h2, rv.x); fma2(acc[5], h2, rv.y);
                fma2(acc[6], h3, rv.x); fma2(acc[7], h3, rv.y);
            }
        }
        // both halves publish their partials
#pragma unroll
        for (int j = 0; j < 8; j++) red[tid * 8 + j] = acc[j];
        __syncthreads();
        // each thread combines and finalizes 2 cells (b = bb+0, bb+1; u = u0+zg)
        {
            const unsigned long long* other = &red[(tid ^ 128) * 8];
            float hn[2];
#pragma unroll
            for (int ii = 0; ii < 2; ii++) {
                int i = kh * 2 + ii;
                unsigned long long z01 = acc[i * 2 + 0];
                unsigned long long z23 = acc[i * 2 + 1];
                add2(z01, other[i * 2 + 0]);
                add2(z23, other[i * 2 + 1]);
                float z0, z1, z2, z3;
                unpack2(z01, z0, z1);
                unpack2(z23, z2, z3);
                z0 += xv[ii].x; z1 += xv[ii].y; z2 += xv[ii].z; z3 += xv[ii].w;
                float ig = sigm_(z0);
                float fg = sigm_(z1);
                float gg = tanh_(z2);
                float og = sigm_(z3);
                float cn = fmaf(fg, cc[ii], ig * gg);
                cc[ii] = cn;
                hn[ii] = og * tanh_(cn);
            }
            int u = u0 + zg;
            *(float2*)(g_hT[wr][dir] + u * BB + bb) = make_float2(hn[0], hn[1]);
            stage[(bgr * 4 + kh * 2 + 0) * 16 + zg] = hn[0];
            stage[(bgr * 4 + kh * 2 + 1) * 16 + zg] = hn[1];
        }
        __syncthreads();

        // ---- group barrier (acq/rel) : arrive early, hide work, wait late ----
        if (tid == 0) {
            int old = atom_add_acqrel(&g_count[grp]);
            if (old == 15) {
                g_count[grp] = 0;
                st_release(&g_gen[grp], s + 1);
            }
        }
        // hidden work: coalesced sequence output [t][b][u]
        if (tid < 128) {
            int row = tid >> 2, q = tid & 3;
            *(float4*)(outb + (size_t)(t * BB + b0 + row) * UU + u0 + q * 4) =
                ((float4*)stage)[tid];
        }
        // hidden work: prefetch xz for next step (independent of h)
        if (s + 1 < TT) {
            int tn2 = dir ? (TT - 2 - s) : (s + 1);
            const float* xp = xzb + (size_t)(tn2 * BB + bb) * ZZ + zc0 + zg * 4;
            xv[0] = *(const float4*)(xp);
            xv[1] = *(const float4*)(xp + ZZ);
        }
        if (tid == 0) {
            while (ld_acquire(&g_gen[grp]) != s + 1) { }
        }
        __syncthreads();
    }
}

// ---------------- merge: out[b][t][u] = 0.5*(h1f + h0f + h1b + h0b) ---------------
__global__ void merge_kernel(float* __restrict__ out) {
    int i = blockIdx.x * blockDim.x + threadIdx.x;
    if (i >= TT * BB * UU / 4) return;
    int u4 = i & 63;
    int b  = (i >> 6) & 127;
    int t  = i >> 13;
    const float4 a = ((const float4*)g_h1[0])[i];
    const float4 c = ((const float4*)g_h0[0])[i];
    const float4 d = ((const float4*)g_h1[1])[i];
    const float4 e = ((const float4*)g_h0[1])[i];
    float4 r;
    r.x = 0.5f * (a.x + c.x + d.x + e.x);
    r.y = 0.5f * (a.y + c.y + d.y + e.y);
    r.z = 0.5f * (a.z + c.z + d.z + e.z);
    r.w = 0.5f * (a.w + c.w + d.w + e.w);
    ((float4*)out)[((b * TT + t) << 6) + u4] = r;
}

// ---------------- launch ----------------------------------------------------------
extern "C" void kernel_launch(void* const* d_in, const int* in_sizes, int n_in,
                              void* d_out, int out_size) {
    const float* x   = (const float*)d_in[0];
    const float* kfw = (const float*)d_in[1];
    const float* rfw = (const float*)d_in[2];
    const float* bfw = (const float*)d_in[3];
    const float* kbw = (const float*)d_in[4];
    const float* rbw = (const float*)d_in[5];
    const float* bbw = (const float*)d_in[6];
    float* out = (float*)d_out;

    const int scan_smem = (UU * 64 + UU * 32 + 256 * 16 + 32 * 16) * (int)sizeof(float); // 116736
    cudaFuncSetAttribute(scan_kernel, cudaFuncAttributeMaxDynamicSharedMemorySize, scan_smem);

    prep_kernel<<<4096, 256>>>(kfw, rfw, bfw, kbw, rbw, bbw);
    for (int layer = 0; layer < 2; layer++) {
        proj_kernel<<<dim3(8, 256, 2), 256>>>(x, layer);
        zero_bar_kernel<<<1, 32>>>();
        scan_kernel<<<NCTA, 256, scan_smem>>>(layer);
    }
    merge_kernel<<<8192, 256>>>(out);
}